// round 8
// baseline (speedup 1.0000x reference)
#include <cuda_runtime.h>
#include <cuda_fp16.h>
#include <cstdint>

// Problem constants
#define N_TOK 2048
#define D_IN  2048
#define D_OUT 2048
#define NE    8
#define NK    4096

// Tiling
#define BM 128
#define BN 128
#define KT 32
#define NT (D_IN / KT)
#define STAGES 4
#define MAX_TILES 40

// smem: s_flat[128] @0, stages @1024. Tile = 128 rows x 32 fp16 (64B rows).
#define SM_FLAT   0
#define SM_TILES  1024
#define TILE_B    8192
#define T_AH 0
#define T_BH TILE_B
#define STAGE_B (2*TILE_B)                      // 16 KB
#define SMEM_TOTAL (SM_TILES + STAGES*STAGE_B)  // 66560

// Device scratch
__device__ __half g_xh[(size_t)N_TOK * D_IN];          // 8 MB
__device__ __half g_wh[(size_t)NE * D_OUT * D_IN];     // 64 MB
__device__ __half g_yh[(size_t)NK * D_OUT];            // 16 MB (fp16 y)

__device__ __forceinline__ uint32_t SW(uint32_t off) {
    return off ^ (((off >> 7) & 3u) << 4);
}

__device__ __forceinline__ uint32_t smem_u32(const void* p) {
    uint32_t a;
    asm("{ .reg .u64 t; cvta.to.shared.u64 t, %1; cvt.u32.u64 %0, t; }" : "=r"(a) : "l"(p));
    return a;
}

__device__ __forceinline__ void cp16(uint32_t dst, const void* src) {
    asm volatile("cp.async.cg.shared.global [%0], [%1], 16;" :: "r"(dst), "l"(src) : "memory");
}
__device__ __forceinline__ void cp_commit() {
    asm volatile("cp.async.commit_group;" ::: "memory");
}
__device__ __forceinline__ void cp_wait2() {
    asm volatile("cp.async.wait_group 2;" ::: "memory");
}

__device__ __forceinline__ void ldm_x4(uint32_t& r0, uint32_t& r1, uint32_t& r2,
                                       uint32_t& r3, uint32_t addr) {
    asm volatile("ldmatrix.sync.aligned.m8n8.x4.shared.b16 {%0,%1,%2,%3}, [%4];"
                 : "=r"(r0), "=r"(r1), "=r"(r2), "=r"(r3) : "r"(addr));
}

__device__ __forceinline__ void mma_fp16(float* c, const uint32_t* a, const uint32_t* b) {
    asm volatile(
        "mma.sync.aligned.m16n8k16.row.col.f32.f16.f16.f32 "
        "{%0,%1,%2,%3}, {%4,%5,%6,%7}, {%8,%9}, {%0,%1,%2,%3};"
        : "+f"(c[0]), "+f"(c[1]), "+f"(c[2]), "+f"(c[3])
        : "r"(a[0]), "r"(a[1]), "r"(a[2]), "r"(a[3]), "r"(b[0]), "r"(b[1]));
}

// ---------------------------------------------------------------------------
// Prepass: x fp32 -> fp16 (8 elems/thread; small)
// ---------------------------------------------------------------------------
__global__ void conv_x_kernel(const float* __restrict__ x) {
    size_t i = ((size_t)blockIdx.x * blockDim.x + threadIdx.x) * 8;
    float4 v0 = *(const float4*)(x + i);
    float4 v1 = *(const float4*)(x + i + 4);
    __half2 h[4];
    h[0] = __floats2half2_rn(v0.x, v0.y);
    h[1] = __floats2half2_rn(v0.z, v0.w);
    h[2] = __floats2half2_rn(v1.x, v1.y);
    h[3] = __floats2half2_rn(v1.z, v1.w);
    *(uint4*)(g_xh + i) = *(uint4*)h;
}

// Prepass: W fp32 -> fp16, 32 elems/thread (MLP=8 uint4 loads in flight)
__global__ __launch_bounds__(256) void conv_w_kernel(const float* __restrict__ w) {
    size_t base = ((size_t)blockIdx.x * blockDim.x + threadIdx.x) * 32;
    float4 v[8];
    #pragma unroll
    for (int q = 0; q < 8; q++) v[q] = *(const float4*)(w + base + 4 * q);
    __half2 h[16];
    #pragma unroll
    for (int q = 0; q < 8; q++) {
        h[2 * q]     = __floats2half2_rn(v[q].x, v[q].y);
        h[2 * q + 1] = __floats2half2_rn(v[q].z, v[q].w);
    }
    #pragma unroll
    for (int q = 0; q < 4; q++)
        *(uint4*)(g_wh + base + 8 * q) = ((uint4*)h)[q];
}

// ---------------------------------------------------------------------------
// Grouped GEMM: 128x128 tile/CTA, 4 warps (64x64 warp tile), cp.async x4
// ---------------------------------------------------------------------------
__global__ __launch_bounds__(128, 2)
void moe_gemm(const int* __restrict__ ssi,
              const int* __restrict__ eoff) {
    const int tile = blockIdx.y;
    int e = -1, m0 = 0, rows = 0;
    {
        int nt = 0, prev = 0;
        #pragma unroll
        for (int ee = 0; ee < NE; ee++) {
            int end = __ldg(eoff + ee);
            int t = (end - prev + BM - 1) >> 7;
            if (e < 0 && tile < nt + t) {
                e = ee;
                m0 = prev + (tile - nt) * BM;
                int rem = end - m0;
                rows = rem < BM ? rem : BM;
            }
            nt += t;
            prev = end;
        }
    }
    if (e < 0) return;
    const int n0 = blockIdx.x * BN;

    extern __shared__ char smem[];
    const uint32_t sb = smem_u32(smem);
    const int tid  = threadIdx.x;
    const int wid  = tid >> 5;
    const int lane = tid & 31;
    const int warp_m = wid & 1;
    const int warp_n = wid >> 1;

    int* s_flat = (int*)(smem + SM_FLAT);
    if (tid < BM) s_flat[tid] = (tid < rows) ? ssi[m0 + tid] : -1;  // guarded (no OOB)
    __syncthreads();

    // cp.async: thread owns chunks {tid + 128q} (q=0..3) of each 512-chunk tile
    const int c16 = (tid & 3) * 8;
    const __half* aptr[4];
    const __half* bptr[4];
    uint32_t dofs[4];
    #pragma unroll
    for (int q = 0; q < 4; q++) {
        const int r = (tid >> 2) + 32 * q;
        const int fl = s_flat[r];
        const int tk = (fl >= 0 ? fl : 0) >> 1;   // clamp invalid rows to token 0
        aptr[q] = g_xh + (size_t)tk * D_IN + c16;
        bptr[q] = g_wh + ((size_t)e * D_OUT + (size_t)(n0 + r)) * D_IN + c16;
        dofs[q] = SW((uint32_t)(r * 64 + (tid & 3) * 16));
    }

    // ldmatrix offsets (proven layout)
    uint32_t a_off[2][4], b_off[2][4];
    #pragma unroll
    for (int s = 0; s < 2; s++) {
        #pragma unroll
        for (int i = 0; i < 4; i++) {
            int arow = warp_m * 64 + i * 16 + (lane & 7) + ((lane >> 3) & 1) * 8;
            int ach  = s * 2 + (lane >> 4);
            a_off[s][i] = SW((uint32_t)(arow * 64 + ach * 16));
        }
        #pragma unroll
        for (int jp = 0; jp < 4; jp++) {
            int brow = warp_n * 64 + (jp * 2 + (lane >> 4)) * 8 + (lane & 7);
            int bch  = s * 2 + ((lane >> 3) & 1);
            b_off[s][jp] = SW((uint32_t)(brow * 64 + bch * 16));
        }
    }

    auto issue = [&](int st, int kt) {
        const uint32_t stg = sb + SM_TILES + (uint32_t)st * STAGE_B;
        const int k = kt * KT;
        #pragma unroll
        for (int q = 0; q < 4; q++) {
            cp16(stg + T_AH + dofs[q], aptr[q] + k);
            cp16(stg + T_BH + dofs[q], bptr[q] + k);
        }
    };

    float acc[4][8][4];
    #pragma unroll
    for (int i = 0; i < 4; i++)
        #pragma unroll
        for (int j = 0; j < 8; j++)
            #pragma unroll
            for (int q = 0; q < 4; q++) acc[i][j][q] = 0.0f;

    #pragma unroll
    for (int s = 0; s < STAGES - 1; s++) { issue(s, s); cp_commit(); }

    for (int it = 0; it < NT; it++) {
        cp_wait2();
        __syncthreads();

        if (it + STAGES - 1 < NT) issue((it + STAGES - 1) & (STAGES - 1), it + STAGES - 1);
        cp_commit();

        const uint32_t stg = sb + SM_TILES + (uint32_t)(it & (STAGES - 1)) * STAGE_B;
        #pragma unroll
        for (int s = 0; s < 2; s++) {
            uint32_t ah[4][4], bh[4][4];
            #pragma unroll
            for (int i = 0; i < 4; i++)
                ldm_x4(ah[i][0], ah[i][1], ah[i][2], ah[i][3], stg + T_AH + a_off[s][i]);
            #pragma unroll
            for (int jp = 0; jp < 4; jp++)
                ldm_x4(bh[jp][0], bh[jp][1], bh[jp][2], bh[jp][3], stg + T_BH + b_off[s][jp]);
            #pragma unroll
            for (int i = 0; i < 4; i++) {
                #pragma unroll
                for (int jp = 0; jp < 4; jp++) {
                    mma_fp16(acc[i][2 * jp],     ah[i], &bh[jp][0]);
                    mma_fp16(acc[i][2 * jp + 1], ah[i], &bh[jp][2]);
                }
            }
        }
        __syncthreads();
    }

    // Epilogue: scatter fp16 y
    #pragma unroll
    for (int i = 0; i < 4; i++) {
        const int mr0 = warp_m * 64 + i * 16 + (lane >> 2);
        const int fl0 = s_flat[mr0];
        const int fl1 = s_flat[mr0 + 8];
        #pragma unroll
        for (int j = 0; j < 8; j++) {
            const int col = n0 + warp_n * 64 + j * 8 + (lane & 3) * 2;
            if (fl0 >= 0) {
                __half2 v = __floats2half2_rn(acc[i][j][0], acc[i][j][1]);
                *(__half2*)(g_yh + (size_t)fl0 * D_OUT + col) = v;
            }
            if (fl1 >= 0) {
                __half2 v = __floats2half2_rn(acc[i][j][2], acc[i][j][3]);
                *(__half2*)(g_yh + (size_t)fl1 * D_OUT + col) = v;
            }
        }
    }
}

// ---------------------------------------------------------------------------
// Combine (fp16 y): out[n, :] = g0*y[2n, :] + g1*y[2n+1, :], 8 cols/thread
// ---------------------------------------------------------------------------
__global__ void combine_kernel(const float* __restrict__ gates,
                               float* __restrict__ out) {
    int idx = blockIdx.x * blockDim.x + threadIdx.x;   // N_TOK * D_OUT / 8
    int n  = idx >> 8;          // D_OUT/8 = 256
    int d8 = idx & 255;
    float g0 = gates[2 * n];
    float g1 = gates[2 * n + 1];
    const uint4 ya = *(const uint4*)(g_yh + (size_t)(2 * n)     * D_OUT + d8 * 8);
    const uint4 yb = *(const uint4*)(g_yh + (size_t)(2 * n + 1) * D_OUT + d8 * 8);
    const __half2* ha = (const __half2*)&ya;
    const __half2* hb = (const __half2*)&yb;
    float4 o[2];
    #pragma unroll
    for (int q = 0; q < 2; q++) {
        float2 a0 = __half22float2(ha[2 * q]);
        float2 a1 = __half22float2(ha[2 * q + 1]);
        float2 b0 = __half22float2(hb[2 * q]);
        float2 b1 = __half22float2(hb[2 * q + 1]);
        o[q] = make_float4(g0 * a0.x + g1 * b0.x, g0 * a0.y + g1 * b0.y,
                           g0 * a1.x + g1 * b1.x, g0 * a1.y + g1 * b1.y);
    }
    float4* dst = (float4*)(out + (size_t)n * D_OUT + d8 * 8);
    dst[0] = o[0];
    dst[1] = o[1];
}

// ---------------------------------------------------------------------------
extern "C" void kernel_launch(void* const* d_in, const int* in_sizes, int n_in,
                              void* d_out, int out_size) {
    const float* x     = (const float*)d_in[0];
    const float* w     = (const float*)d_in[1];
    const int*   ssi   = (const int*)  d_in[4];
    const int*   eoff  = (const int*)  d_in[6];
    const float* gates = (const float*)d_in[7];
    float* out = (float*)d_out;

    conv_x_kernel<<<(N_TOK * D_IN) / (256 * 8), 256>>>(x);
    conv_w_kernel<<<(NE * D_OUT * D_IN) / (256 * 32), 256>>>(w);

    cudaFuncSetAttribute(moe_gemm,
                         cudaFuncAttributeMaxDynamicSharedMemorySize, SMEM_TOTAL);
    dim3 grid(D_OUT / BN, MAX_TILES);
    moe_gemm<<<grid, 128, SMEM_TOTAL>>>(ssi, eoff);

    combine_kernel<<<(N_TOK * (D_OUT / 8)) / 256, 256>>>(gates, out);
}

// round 9
// speedup vs baseline: 1.0891x; 1.0891x over previous
#include <cuda_runtime.h>
#include <cuda_fp16.h>
#include <cstdint>

// Problem constants
#define N_TOK 2048
#define D_IN  2048
#define D_OUT 2048
#define NE    8
#define NK    4096

// Tiling
#define BM 128
#define BN 128
#define KT 32
#define NT (D_IN / KT)
#define STAGES 4
#define MAX_TILES 40

// smem: s_flat[128] @0, stages @1024. Tile = 128 rows x 32 fp16 (64B rows).
#define SM_FLAT   0
#define SM_TILES  1024
#define TILE_B    8192
#define T_AH 0
#define T_BH TILE_B
#define STAGE_B (2*TILE_B)                      // 16 KB
#define SMEM_TOTAL (SM_TILES + STAGES*STAGE_B)  // 66560

// Device scratch
__device__ __half g_xh[(size_t)N_TOK * D_IN];          // 8 MB
__device__ __half g_wh[(size_t)NE * D_OUT * D_IN];     // 64 MB
__device__ __half g_yh[(size_t)NK * D_OUT];            // 16 MB

__device__ __forceinline__ uint32_t SW(uint32_t off) {
    return off ^ (((off >> 7) & 3u) << 4);
}

__device__ __forceinline__ uint32_t smem_u32(const void* p) {
    uint32_t a;
    asm("{ .reg .u64 t; cvta.to.shared.u64 t, %1; cvt.u32.u64 %0, t; }" : "=r"(a) : "l"(p));
    return a;
}

__device__ __forceinline__ void cp16(uint32_t dst, const void* src) {
    asm volatile("cp.async.cg.shared.global [%0], [%1], 16;" :: "r"(dst), "l"(src) : "memory");
}
__device__ __forceinline__ void cp_commit() {
    asm volatile("cp.async.commit_group;" ::: "memory");
}
__device__ __forceinline__ void cp_wait2() {
    asm volatile("cp.async.wait_group 2;" ::: "memory");
}

__device__ __forceinline__ void ldm_x4(uint32_t& r0, uint32_t& r1, uint32_t& r2,
                                       uint32_t& r3, uint32_t addr) {
    asm volatile("ldmatrix.sync.aligned.m8n8.x4.shared.b16 {%0,%1,%2,%3}, [%4];"
                 : "=r"(r0), "=r"(r1), "=r"(r2), "=r"(r3) : "r"(addr));
}

__device__ __forceinline__ void mma_fp16(float* c, const uint32_t* a, const uint32_t* b) {
    asm volatile(
        "mma.sync.aligned.m16n8k16.row.col.f32.f16.f16.f32 "
        "{%0,%1,%2,%3}, {%4,%5,%6,%7}, {%8,%9}, {%0,%1,%2,%3};"
        : "+f"(c[0]), "+f"(c[1]), "+f"(c[2]), "+f"(c[3])
        : "r"(a[0]), "r"(a[1]), "r"(a[2]), "r"(a[3]), "r"(b[0]), "r"(b[1]));
}

// ---------------------------------------------------------------------------
// Coalesced MLP=8 fp32->fp16 conversion. Each of the 8 loads/stores is
// warp-contiguous (stride = 256 float4 between a thread's accesses).
// Block handles 2048 float4s = 8192 floats.
// ---------------------------------------------------------------------------
__device__ __forceinline__ void conv_block(const float4* __restrict__ src4,
                                           uint2* __restrict__ dst2) {
    const size_t base = (size_t)blockIdx.x * 2048 + threadIdx.x;
    float4 v[8];
    #pragma unroll
    for (int q = 0; q < 8; q++) v[q] = src4[base + 256 * q];
    uint2 o[8];
    #pragma unroll
    for (int q = 0; q < 8; q++) {
        __half2 h0 = __floats2half2_rn(v[q].x, v[q].y);
        __half2 h1 = __floats2half2_rn(v[q].z, v[q].w);
        o[q] = make_uint2(*(uint32_t*)&h0, *(uint32_t*)&h1);
    }
    #pragma unroll
    for (int q = 0; q < 8; q++) dst2[base + 256 * q] = o[q];
}

__global__ __launch_bounds__(256) void conv_x_kernel(const float* __restrict__ x) {
    conv_block((const float4*)x, (uint2*)g_xh);
}
__global__ __launch_bounds__(256) void conv_w_kernel(const float* __restrict__ w) {
    conv_block((const float4*)w, (uint2*)g_wh);
}

// ---------------------------------------------------------------------------
// Grouped GEMM: 128x128 tile/CTA, 4 warps (64x64 warp tile), cp.async x4
// ---------------------------------------------------------------------------
__global__ __launch_bounds__(128, 2)
void moe_gemm(const int* __restrict__ ssi,
              const int* __restrict__ eoff) {
    const int tile = blockIdx.y;
    int e = -1, m0 = 0, rows = 0;
    {
        int nt = 0, prev = 0;
        #pragma unroll
        for (int ee = 0; ee < NE; ee++) {
            int end = __ldg(eoff + ee);
            int t = (end - prev + BM - 1) >> 7;
            if (e < 0 && tile < nt + t) {
                e = ee;
                m0 = prev + (tile - nt) * BM;
                int rem = end - m0;
                rows = rem < BM ? rem : BM;
            }
            nt += t;
            prev = end;
        }
    }
    if (e < 0) return;
    const int n0 = blockIdx.x * BN;

    extern __shared__ char smem[];
    const uint32_t sb = smem_u32(smem);
    const int tid  = threadIdx.x;
    const int wid  = tid >> 5;
    const int lane = tid & 31;
    const int warp_m = wid & 1;
    const int warp_n = wid >> 1;

    int* s_flat = (int*)(smem + SM_FLAT);
    if (tid < BM) s_flat[tid] = (tid < rows) ? ssi[m0 + tid] : -1;
    __syncthreads();

    const int c16 = (tid & 3) * 8;
    const __half* aptr[4];
    const __half* bptr[4];
    uint32_t dofs[4];
    #pragma unroll
    for (int q = 0; q < 4; q++) {
        const int r = (tid >> 2) + 32 * q;
        const int fl = s_flat[r];
        const int tk = (fl >= 0 ? fl : 0) >> 1;
        aptr[q] = g_xh + (size_t)tk * D_IN + c16;
        bptr[q] = g_wh + ((size_t)e * D_OUT + (size_t)(n0 + r)) * D_IN + c16;
        dofs[q] = SW((uint32_t)(r * 64 + (tid & 3) * 16));
    }

    uint32_t a_off[2][4], b_off[2][4];
    #pragma unroll
    for (int s = 0; s < 2; s++) {
        #pragma unroll
        for (int i = 0; i < 4; i++) {
            int arow = warp_m * 64 + i * 16 + (lane & 7) + ((lane >> 3) & 1) * 8;
            int ach  = s * 2 + (lane >> 4);
            a_off[s][i] = SW((uint32_t)(arow * 64 + ach * 16));
        }
        #pragma unroll
        for (int jp = 0; jp < 4; jp++) {
            int brow = warp_n * 64 + (jp * 2 + (lane >> 4)) * 8 + (lane & 7);
            int bch  = s * 2 + ((lane >> 3) & 1);
            b_off[s][jp] = SW((uint32_t)(brow * 64 + bch * 16));
        }
    }

    auto issue = [&](int st, int kt) {
        const uint32_t stg = sb + SM_TILES + (uint32_t)st * STAGE_B;
        const int k = kt * KT;
        #pragma unroll
        for (int q = 0; q < 4; q++) {
            cp16(stg + T_AH + dofs[q], aptr[q] + k);
            cp16(stg + T_BH + dofs[q], bptr[q] + k);
        }
    };

    float acc[4][8][4];
    #pragma unroll
    for (int i = 0; i < 4; i++)
        #pragma unroll
        for (int j = 0; j < 8; j++)
            #pragma unroll
            for (int q = 0; q < 4; q++) acc[i][j][q] = 0.0f;

    #pragma unroll
    for (int s = 0; s < STAGES - 1; s++) { issue(s, s); cp_commit(); }

    for (int it = 0; it < NT; it++) {
        cp_wait2();
        __syncthreads();

        if (it + STAGES - 1 < NT) issue((it + STAGES - 1) & (STAGES - 1), it + STAGES - 1);
        cp_commit();

        const uint32_t stg = sb + SM_TILES + (uint32_t)(it & (STAGES - 1)) * STAGE_B;
        #pragma unroll
        for (int s = 0; s < 2; s++) {
            uint32_t ah[4][4], bh[4][4];
            #pragma unroll
            for (int i = 0; i < 4; i++)
                ldm_x4(ah[i][0], ah[i][1], ah[i][2], ah[i][3], stg + T_AH + a_off[s][i]);
            #pragma unroll
            for (int jp = 0; jp < 4; jp++)
                ldm_x4(bh[jp][0], bh[jp][1], bh[jp][2], bh[jp][3], stg + T_BH + b_off[s][jp]);
            #pragma unroll
            for (int i = 0; i < 4; i++) {
                #pragma unroll
                for (int jp = 0; jp < 4; jp++) {
                    mma_fp16(acc[i][2 * jp],     ah[i], &bh[jp][0]);
                    mma_fp16(acc[i][2 * jp + 1], ah[i], &bh[jp][2]);
                }
            }
        }
        __syncthreads();
    }

    // Epilogue: fp16 y scatter
    #pragma unroll
    for (int i = 0; i < 4; i++) {
        const int mr0 = warp_m * 64 + i * 16 + (lane >> 2);
        const int fl0 = s_flat[mr0];
        const int fl1 = s_flat[mr0 + 8];
        #pragma unroll
        for (int j = 0; j < 8; j++) {
            const int col = n0 + warp_n * 64 + j * 8 + (lane & 3) * 2;
            if (fl0 >= 0) {
                __half2 v = __floats2half2_rn(acc[i][j][0], acc[i][j][1]);
                *(__half2*)(g_yh + (size_t)fl0 * D_OUT + col) = v;
            }
            if (fl1 >= 0) {
                __half2 v = __floats2half2_rn(acc[i][j][2], acc[i][j][3]);
                *(__half2*)(g_yh + (size_t)fl1 * D_OUT + col) = v;
            }
        }
    }
}

// ---------------------------------------------------------------------------
// Combine (fp16 y): out[n, :] = g0*y[2n, :] + g1*y[2n+1, :]
// ---------------------------------------------------------------------------
__global__ void combine_kernel(const float* __restrict__ gates,
                               float* __restrict__ out) {
    int idx = blockIdx.x * blockDim.x + threadIdx.x;
    int n  = idx >> 8;
    int d8 = idx & 255;
    float g0 = gates[2 * n];
    float g1 = gates[2 * n + 1];
    const uint4 ya = *(const uint4*)(g_yh + (size_t)(2 * n)     * D_OUT + d8 * 8);
    const uint4 yb = *(const uint4*)(g_yh + (size_t)(2 * n + 1) * D_OUT + d8 * 8);
    const __half2* ha = (const __half2*)&ya;
    const __half2* hb = (const __half2*)&yb;
    float4 o[2];
    #pragma unroll
    for (int q = 0; q < 2; q++) {
        float2 a0 = __half22float2(ha[2 * q]);
        float2 a1 = __half22float2(ha[2 * q + 1]);
        float2 b0 = __half22float2(hb[2 * q]);
        float2 b1 = __half22float2(hb[2 * q + 1]);
        o[q] = make_float4(g0 * a0.x + g1 * b0.x, g0 * a0.y + g1 * b0.y,
                           g0 * a1.x + g1 * b1.x, g0 * a1.y + g1 * b1.y);
    }
    float4* dst = (float4*)(out + (size_t)n * D_OUT + d8 * 8);
    dst[0] = o[0];
    dst[1] = o[1];
}

// ---------------------------------------------------------------------------
extern "C" void kernel_launch(void* const* d_in, const int* in_sizes, int n_in,
                              void* d_out, int out_size) {
    const float* x     = (const float*)d_in[0];
    const float* w     = (const float*)d_in[1];
    const int*   ssi   = (const int*)  d_in[4];
    const int*   eoff  = (const int*)  d_in[6];
    const float* gates = (const float*)d_in[7];
    float* out = (float*)d_out;

    conv_x_kernel<<<(N_TOK * D_IN) / 8192, 256>>>(x);           // 512 blocks
    conv_w_kernel<<<(NE * D_OUT * D_IN) / 8192, 256>>>(w);      // 4096 blocks

    cudaFuncSetAttribute(moe_gemm,
                         cudaFuncAttributeMaxDynamicSharedMemorySize, SMEM_TOTAL);
    dim3 grid(D_OUT / BN, MAX_TILES);
    moe_gemm<<<grid, 128, SMEM_TOTAL>>>(ssi, eoff);

    combine_kernel<<<(N_TOK * (D_OUT / 8)) / 256, 256>>>(gates, out);
}